// round 13
// baseline (speedup 1.0000x reference)
#include <cuda_runtime.h>
#include <cuda_fp16.h>
#include <cstdint>

#define NTH 128
#define BN 64
#define MAX_BH 32
#define MAX_T  32

#define KVBLK 16640          // KH 8192 + V 8192 + D2 256

// static scratch (allowed: __device__ globals, no runtime alloc)
__device__ __align__(1024) uint8_t g_kv[(size_t)MAX_BH * MAX_T * KVBLK];

#define SWZ(x) ((x) ^ (((x) >> 3) & 0x70))

__device__ __forceinline__ uint32_t smem_u32(const void* p) {
    uint32_t a;
    asm("{ .reg .u64 t; cvta.to.shared.u64 t, %1; cvt.u32.u64 %0, t; }" : "=r"(a) : "l"(p));
    return a;
}
__device__ __forceinline__ float ex2f(float x) {
    float r; asm("ex2.approx.f32 %0, %1;" : "=f"(r) : "f"(x)); return r;
}
__device__ __forceinline__ uint32_t pack_h2(float a, float b) {
    uint32_t d; asm("cvt.rn.f16x2.f32 %0, %1, %2;" : "=r"(d) : "f"(b), "f"(a)); return d;
}
__device__ __forceinline__ void ldsm4(uint32_t* r, uint32_t addr) {
    asm volatile("ldmatrix.sync.aligned.m8n8.x4.shared.b16 {%0,%1,%2,%3}, [%4];"
        : "=r"(r[0]), "=r"(r[1]), "=r"(r[2]), "=r"(r[3]) : "r"(addr));
}
__device__ __forceinline__ void ldsm4t(uint32_t* r, uint32_t addr) {
    asm volatile("ldmatrix.sync.aligned.m8n8.x4.trans.shared.b16 {%0,%1,%2,%3}, [%4];"
        : "=r"(r[0]), "=r"(r[1]), "=r"(r[2]), "=r"(r[3]) : "r"(addr));
}
__device__ __forceinline__ void mma16816(float* c, const uint32_t* a, uint32_t b0, uint32_t b1) {
    asm volatile("mma.sync.aligned.m16n8k16.row.col.f32.f16.f16.f32 "
        "{%0,%1,%2,%3}, {%4,%5,%6,%7}, {%8,%9}, {%0,%1,%2,%3};"
        : "+f"(c[0]), "+f"(c[1]), "+f"(c[2]), "+f"(c[3])
        : "r"(a[0]), "r"(a[1]), "r"(a[2]), "r"(a[3]), "r"(b0), "r"(b1));
}
__device__ __forceinline__ void cpa16(uint32_t s, const void* g) {
    asm volatile("cp.async.cg.shared.global [%0], [%1], 16;" :: "r"(s), "l"(g));
}
__device__ __forceinline__ void cpa_commit() {
    asm volatile("cp.async.commit_group;" ::: "memory");
}
template <int N>
__device__ __forceinline__ void cpa_wait() {
    asm volatile("cp.async.wait_group %0;" :: "n"(N) : "memory");
}

// ---------------- preprocess: K->f16, V->f16, d2; smem-image (swizzled) layout --------
__global__ void __launch_bounds__(NTH)
prep_kernel(const float* __restrict__ Kg, const float* __restrict__ Vg,
            const float* __restrict__ deltag, int B, int L, int H)
{
    const int BH = B * H;
    const int numT = L / 64;
    const int bid = blockIdx.x;
    const int t  = bid / BH;
    const int bh = bid % BH;
    const int b = bh / H, h = bh % H;
    const int tid = threadIdx.x;

    const int stride = H * 64;
    const size_t head_off = (size_t)b * L * stride + (size_t)h * 64;
    const int r0 = t * 64;

    uint8_t* kvb = g_kv + (size_t)(bh * numT + t) * KVBLK;

    #pragma unroll
    for (int i = 0; i < 8; i++) {
        int idx = tid + NTH * i;            // 1024 float4s per 64x64 tile
        int row = idx >> 4, c4 = idx & 15;
        uint32_t off = SWZ((uint32_t)(row * 128 + c4 * 8));
        const size_t goff = head_off + (size_t)(r0 + row) * stride + c4 * 4;

        float4 k = *(const float4*)(Kg + goff);
        *(uint2*)(kvb + off) = make_uint2(pack_h2(k.x, k.y), pack_h2(k.z, k.w));

        float4 vv = *(const float4*)(Vg + goff);
        *(uint2*)(kvb + 8192 + off) = make_uint2(pack_h2(vv.x, vv.y), pack_h2(vv.z, vv.w));
    }
    const float LOG2E = 1.4426950408889634f;
    if (tid < 64)
        ((float*)(kvb + 16384))[tid] = deltag[(size_t)b * L + r0 + tid] * (0.125f * LOG2E);
}

// ---------------- main: 128 q-rows/CTA, cp.async double-buffered ----------------
#define STG0 16384            // stages after Q region (QH 16KB, 128 rows)
#define SMEM_MAIN (16384 + 2 * KVBLK + 1024)

__global__ void __launch_bounds__(NTH, 3)
dsattn_mma(const float* __restrict__ Qg, const float* __restrict__ taug,
           float* __restrict__ Og, int B, int L, int H)
{
    extern __shared__ __align__(1024) char smraw[];
    const uint32_t raw32 = smem_u32(smraw);
    const uint32_t sb = (raw32 + 1023u) & ~1023u;
    char* sm = smraw + (sb - raw32);

    const int tid  = threadIdx.x;
    const int wid  = tid >> 5;
    const int lane = tid & 31;
    const int gid  = lane >> 2;
    const int tig  = lane & 3;

    const int numQT = L / 128;           // 128-row q-tiles
    const int BH = B * H;
    const int qt = numQT - 1 - ((int)blockIdx.x / BH);   // LPT: big q-tiles first
    const int bh = (int)blockIdx.x % BH;
    const int b = bh / H, h = bh % H;

    const int stride = H * 64;
    const size_t head_off = (size_t)b * L * stride + (size_t)h * 64;
    const float* qbase = Qg + head_off;
    const uint8_t* kvrow = g_kv + (size_t)bh * (L / 64) * KVBLK;

    const float LOG2E = 1.4426950408889634f;
    const float f2 = taug[b] * 0.125f * LOG2E;
    const int q0 = qt * 128;
    const int ntmax = 2 * qt + 1;        // last 64-key tile index

    // ---- issue stage-0 prefetch first, convert Q behind it ----
    {
        const uint8_t* src = kvrow;
        #pragma unroll
        for (int j = 0; j < 8; j++) {
            int ch = tid + j * NTH;
            cpa16(sb + STG0 + ch * 16, src + ch * 16);
        }
        if (tid < 16) cpa16(sb + STG0 + 16384 + tid * 16, src + 16384 + tid * 16);
        cpa_commit();
    }

    // ---- Q tile (128 rows): scale, f16, swizzled panel ----
    #pragma unroll
    for (int i = 0; i < 16; i++) {
        int idx = tid + NTH * i;         // 2048 float4s
        int row = idx >> 4, c4 = idx & 15;
        float4 v = *(const float4*)(qbase + (size_t)(q0 + row) * stride + c4 * 4);
        v.x *= f2; v.y *= f2; v.z *= f2; v.w *= f2;
        uint32_t off = SWZ((uint32_t)(row * 128 + c4 * 8));
        *(uint2*)(sm + off) = make_uint2(pack_h2(v.x, v.y), pack_h2(v.z, v.w));
    }
    __syncthreads();

    // ---- Q fragments: two 16-row m-frags per warp (rows wid*32 .. wid*32+31) ----
    uint32_t qh0[4][4], qh1[4][4];
    {
        int rowq = wid * 32 + (lane & 15);
        int csel = (lane >> 4) * 16;
        #pragma unroll
        for (int m = 0; m < 4; m++) {
            uint32_t off0 = SWZ((uint32_t)(rowq * 128 + m * 32 + csel));
            uint32_t off1 = SWZ((uint32_t)((rowq + 16) * 128 + m * 32 + csel));
            ldsm4(qh0[m], sb + off0);
            ldsm4(qh1[m], sb + off1);
        }
    }

    float o0[8][4], o1[8][4];
    #pragma unroll
    for (int j = 0; j < 8; j++)
        #pragma unroll
        for (int c = 0; c < 4; c++) { o0[j][c] = 0.f; o1[j][c] = 0.f; }
    float ls00 = 0.f, ls08 = 0.f, ls16 = 0.f, ls24 = 0.f;
    const int qg0 = q0 + wid * 32 + gid;     // mi0 rows: qg0, qg0+8; mi1: +16, +24

    for (int nt = 0; nt <= ntmax; nt++) {
        const int n0 = nt * BN;
        const uint32_t stg = sb + STG0 + (uint32_t)(nt & 1) * KVBLK;

        // prefetch next stage, then wait for current
        if (nt + 1 <= ntmax) {
            const uint8_t* src = kvrow + (size_t)(nt + 1) * KVBLK;
            const uint32_t dst = sb + STG0 + (uint32_t)((nt + 1) & 1) * KVBLK;
            #pragma unroll
            for (int j = 0; j < 8; j++) {
                int ch = tid + j * NTH;
                cpa16(dst + ch * 16, src + ch * 16);
            }
            if (tid < 16) cpa16(dst + 16384 + tid * 16, src + 16384 + tid * 16);
            cpa_commit();
            cpa_wait<1>();
        } else {
            cpa_wait<0>();
        }
        __syncthreads();

        const float* D2 = (const float*)(sm + (stg - sb) + 16384);
        const bool diag = (nt >= 2 * qt);     // tiles intersecting the causal boundary
        const int rowk = ((lane >> 4) << 3) + (lane & 7);
        const int csub = ((lane >> 3) & 1);
        const int rowv = ((lane >> 3) & 1) * 8 + (lane & 7);
        const int csel = (lane >> 4);

        #pragma unroll
        for (int h2 = 0; h2 < 2; h2++) {
            // ---- S for both m-frags, 32 keys: each K fragment used twice ----
            float s0[4][4], s1[4][4];
            #pragma unroll
            for (int jl = 0; jl < 4; jl++)
                #pragma unroll
                for (int c = 0; c < 4; c++) { s0[jl][c] = 0.f; s1[jl][c] = 0.f; }
            #pragma unroll
            for (int m = 0; m < 4; m++) {
                #pragma unroll
                for (int j2 = 0; j2 < 2; j2++) {
                    int jj = 2 * h2 + j2;
                    uint32_t off = SWZ((uint32_t)((jj * 16 + rowk) * 128 + (m * 2 + csub) * 16));
                    uint32_t kb[4];
                    ldsm4(kb, stg + off);
                    mma16816(s0[2 * j2],     qh0[m], kb[0], kb[1]);
                    mma16816(s0[2 * j2 + 1], qh0[m], kb[2], kb[3]);
                    mma16816(s1[2 * j2],     qh1[m], kb[0], kb[1]);
                    mma16816(s1[2 * j2 + 1], qh1[m], kb[2], kb[3]);
                }
            }

            // ---- softmax both m-frags, pack P to f16 ----
            uint32_t pa0[2][4], pa1[2][4];
            #pragma unroll
            for (int jl = 0; jl < 4; jl++) {
                int lc = 8 * (4 * h2 + jl) + 2 * tig;
                float d0 = D2[lc], d1 = D2[lc + 1];
                int sg = n0 + lc;
                int ml = jl >> 1, hs = (jl & 1) * 2;

                float p0 = ex2f(s0[jl][0] + d0);
                float p1 = ex2f(s0[jl][1] + d1);
                float p2 = ex2f(s0[jl][2] + d0);
                float p3 = ex2f(s0[jl][3] + d1);
                if (diag) {
                    if (sg     > qg0)     p0 = 0.f;
                    if (sg + 1 > qg0)     p1 = 0.f;
                    if (sg     > qg0 + 8) p2 = 0.f;
                    if (sg + 1 > qg0 + 8) p3 = 0.f;
                }
                ls00 += p0 + p1;
                ls08 += p2 + p3;
                pa0[ml][hs]     = pack_h2(p0, p1);
                pa0[ml][hs + 1] = pack_h2(p2, p3);

                float r0 = ex2f(s1[jl][0] + d0);
                float r1 = ex2f(s1[jl][1] + d1);
                float r2 = ex2f(s1[jl][2] + d0);
                float r3 = ex2f(s1[jl][3] + d1);
                if (diag) {
                    if (sg     > qg0 + 16) r0 = 0.f;
                    if (sg + 1 > qg0 + 16) r1 = 0.f;
                    if (sg     > qg0 + 24) r2 = 0.f;
                    if (sg + 1 > qg0 + 24) r3 = 0.f;
                }
                ls16 += r0 + r1;
                ls24 += r2 + r3;
                pa1[ml][hs]     = pack_h2(r0, r1);
                pa1[ml][hs + 1] = pack_h2(r2, r3);
            }

            // ---- O += P @ V: each V fragment used twice ----
            #pragma unroll
            for (int ml = 0; ml < 2; ml++) {
                int mg = 2 * h2 + ml;
                #pragma unroll
                for (int jj = 0; jj < 4; jj++) {
                    uint32_t off = SWZ((uint32_t)((mg * 16 + rowv) * 128 + (2 * jj + csel) * 16));
                    uint32_t vb[4];
                    ldsm4t(vb, stg + 8192 + off);
                    mma16816(o0[2 * jj],     pa0[ml], vb[0], vb[1]);
                    mma16816(o0[2 * jj + 1], pa0[ml], vb[2], vb[3]);
                    mma16816(o1[2 * jj],     pa1[ml], vb[0], vb[1]);
                    mma16816(o1[2 * jj + 1], pa1[ml], vb[2], vb[3]);
                }
            }
        }
        __syncthreads();   // stage buffer free before refill
    }

    // ---- reduce l, write O ----
    ls00 += __shfl_xor_sync(0xffffffffu, ls00, 1);
    ls00 += __shfl_xor_sync(0xffffffffu, ls00, 2);
    ls08 += __shfl_xor_sync(0xffffffffu, ls08, 1);
    ls08 += __shfl_xor_sync(0xffffffffu, ls08, 2);
    ls16 += __shfl_xor_sync(0xffffffffu, ls16, 1);
    ls16 += __shfl_xor_sync(0xffffffffu, ls16, 2);
    ls24 += __shfl_xor_sync(0xffffffffu, ls24, 1);
    ls24 += __shfl_xor_sync(0xffffffffu, ls24, 2);
    const float i00 = 1.0f / ls00;
    const float i08 = 1.0f / ls08;
    const float i16 = 1.0f / ls16;
    const float i24 = 1.0f / ls24;

    {
        float* r00 = Og + head_off + (size_t)qg0 * stride;
        float* r08 = r00 + (size_t)8  * stride;
        float* r16 = r00 + (size_t)16 * stride;
        float* r24 = r00 + (size_t)24 * stride;
        #pragma unroll
        for (int j = 0; j < 8; j++) {
            int col = 8 * j + 2 * tig;
            *(float2*)(r00 + col) = make_float2(o0[j][0] * i00, o0[j][1] * i00);
            *(float2*)(r08 + col) = make_float2(o0[j][2] * i08, o0[j][3] * i08);
            *(float2*)(r16 + col) = make_float2(o1[j][0] * i16, o1[j][1] * i16);
            *(float2*)(r24 + col) = make_float2(o1[j][2] * i24, o1[j][3] * i24);
        }
    }
}

extern "C" void kernel_launch(void* const* d_in, const int* in_sizes, int n_in,
                              void* d_out, int out_size) {
    const float* Q     = (const float*)d_in[0];
    const float* K     = (const float*)d_in[1];
    const float* V     = (const float*)d_in[2];
    const float* tau   = (const float*)d_in[3];
    const float* delta = (const float*)d_in[4];
    float* O = (float*)d_out;

    const int B = in_sizes[3];
    const int L = in_sizes[4] / B;
    const int H = in_sizes[0] / (B * L * 64);
    const int BH = B * H;

    static bool attr_set = false;
    if (!attr_set) {
        cudaFuncSetAttribute(dsattn_mma, cudaFuncAttributeMaxDynamicSharedMemorySize, SMEM_MAIN);
        attr_set = true;
    }

    prep_kernel<<<BH * (L / 64), NTH>>>(K, V, delta, B, L, H);
    dsattn_mma<<<(L / 128) * BH, NTH, SMEM_MAIN>>>(Q, tau, O, B, L, H);
}

// round 14
// speedup vs baseline: 1.1516x; 1.1516x over previous
#include <cuda_runtime.h>
#include <cuda_fp16.h>
#include <cstdint>

#define NTH 128
#define BN 64
#define MAX_BH 32
#define MAX_T  32

#define KVBLK 16640          // KH 8192 + V 8192 + D2 256

// static scratch (allowed: __device__ globals, no runtime alloc)
__device__ __align__(1024) uint8_t g_kv[(size_t)MAX_BH * MAX_T * KVBLK];

#define SWZ(x) ((x) ^ (((x) >> 3) & 0x70))

__device__ __forceinline__ uint32_t smem_u32(const void* p) {
    uint32_t a;
    asm("{ .reg .u64 t; cvta.to.shared.u64 t, %1; cvt.u32.u64 %0, t; }" : "=r"(a) : "l"(p));
    return a;
}
__device__ __forceinline__ float ex2f(float x) {
    float r; asm("ex2.approx.f32 %0, %1;" : "=f"(r) : "f"(x)); return r;
}
__device__ __forceinline__ uint32_t pack_h2(float a, float b) {
    uint32_t d; asm("cvt.rn.f16x2.f32 %0, %1, %2;" : "=r"(d) : "f"(b), "f"(a)); return d;
}
__device__ __forceinline__ void ldsm4(uint32_t* r, uint32_t addr) {
    asm volatile("ldmatrix.sync.aligned.m8n8.x4.shared.b16 {%0,%1,%2,%3}, [%4];"
        : "=r"(r[0]), "=r"(r[1]), "=r"(r[2]), "=r"(r[3]) : "r"(addr));
}
__device__ __forceinline__ void ldsm4t(uint32_t* r, uint32_t addr) {
    asm volatile("ldmatrix.sync.aligned.m8n8.x4.trans.shared.b16 {%0,%1,%2,%3}, [%4];"
        : "=r"(r[0]), "=r"(r[1]), "=r"(r[2]), "=r"(r[3]) : "r"(addr));
}
__device__ __forceinline__ void mma16816(float* c, const uint32_t* a, uint32_t b0, uint32_t b1) {
    asm volatile("mma.sync.aligned.m16n8k16.row.col.f32.f16.f16.f32 "
        "{%0,%1,%2,%3}, {%4,%5,%6,%7}, {%8,%9}, {%0,%1,%2,%3};"
        : "+f"(c[0]), "+f"(c[1]), "+f"(c[2]), "+f"(c[3])
        : "r"(a[0]), "r"(a[1]), "r"(a[2]), "r"(a[3]), "r"(b0), "r"(b1));
}
__device__ __forceinline__ void cpa16(uint32_t s, const void* g) {
    asm volatile("cp.async.cg.shared.global [%0], [%1], 16;" :: "r"(s), "l"(g));
}
__device__ __forceinline__ void cpa_commit() {
    asm volatile("cp.async.commit_group;" ::: "memory");
}
template <int N>
__device__ __forceinline__ void cpa_wait() {
    asm volatile("cp.async.wait_group %0;" :: "n"(N) : "memory");
}

// ---------------- preprocess: K->f16, V->f16, d2; smem-image (swizzled) layout --------
__global__ void __launch_bounds__(NTH)
prep_kernel(const float* __restrict__ Kg, const float* __restrict__ Vg,
            const float* __restrict__ deltag, int B, int L, int H)
{
    const int BH = B * H;
    const int numT = L / 64;
    const int bid = blockIdx.x;
    const int t  = bid / BH;
    const int bh = bid % BH;
    const int b = bh / H, h = bh % H;
    const int tid = threadIdx.x;

    const int stride = H * 64;
    const size_t head_off = (size_t)b * L * stride + (size_t)h * 64;
    const int r0 = t * 64;

    uint8_t* kvb = g_kv + (size_t)(bh * numT + t) * KVBLK;

    #pragma unroll
    for (int i = 0; i < 8; i++) {
        int idx = tid + NTH * i;            // 1024 float4s per 64x64 tile
        int row = idx >> 4, c4 = idx & 15;
        uint32_t off = SWZ((uint32_t)(row * 128 + c4 * 8));
        const size_t goff = head_off + (size_t)(r0 + row) * stride + c4 * 4;

        float4 k = *(const float4*)(Kg + goff);
        *(uint2*)(kvb + off) = make_uint2(pack_h2(k.x, k.y), pack_h2(k.z, k.w));

        float4 vv = *(const float4*)(Vg + goff);
        *(uint2*)(kvb + 8192 + off) = make_uint2(pack_h2(vv.x, vv.y), pack_h2(vv.z, vv.w));
    }
    const float LOG2E = 1.4426950408889634f;
    if (tid < 64)
        ((float*)(kvb + 16384))[tid] = deltag[(size_t)b * L + r0 + tid] * (0.125f * LOG2E);
}

// ---------------- main: warp = (qpair, khalf); cp.async double-buffered ----------------
#define STG0 8192             // stages after Q region (QH 8KB)
#define SMEM_MAIN (8192 + 2 * KVBLK + 1024)

__global__ void __launch_bounds__(NTH, 3)
dsattn_mma(const float* __restrict__ Qg, const float* __restrict__ taug,
           float* __restrict__ Og, int B, int L, int H)
{
    extern __shared__ __align__(1024) char smraw[];
    const uint32_t raw32 = smem_u32(smraw);
    const uint32_t sb = (raw32 + 1023u) & ~1023u;
    char* sm = smraw + (sb - raw32);

    const int tid  = threadIdx.x;
    const int wid  = tid >> 5;
    const int lane = tid & 31;
    const int gid  = lane >> 2;
    const int tig  = lane & 3;
    const int qpair = wid >> 1;          // 0: q-rows 0-31, 1: q-rows 32-63
    const int khalf = wid & 1;           // 0: keys 0-31 of tile, 1: keys 32-63

    const int numQT = L / 64;
    const int BH = B * H;
    const int qt = numQT - 1 - ((int)blockIdx.x / BH);   // LPT: big q-tiles first
    const int bh = (int)blockIdx.x % BH;
    const int b = bh / H, h = bh % H;

    const int stride = H * 64;
    const size_t head_off = (size_t)b * L * stride + (size_t)h * 64;
    const float* qbase = Qg + head_off;
    const uint8_t* kvrow = g_kv + (size_t)bh * numQT * KVBLK;

    const float LOG2E = 1.4426950408889634f;
    const float f2 = taug[b] * 0.125f * LOG2E;
    const int q0 = qt * 64;

    // ---- issue stage-0 prefetch first, convert Q behind it ----
    {
        const uint8_t* src = kvrow;
        #pragma unroll
        for (int j = 0; j < 8; j++) {
            int ch = tid + j * NTH;
            cpa16(sb + STG0 + ch * 16, src + ch * 16);
        }
        if (tid < 16) cpa16(sb + STG0 + 16384 + tid * 16, src + 16384 + tid * 16);
        cpa_commit();
    }

    // ---- Q tile (64 rows): scale, f16, swizzled panel ----
    #pragma unroll
    for (int i = 0; i < 8; i++) {
        int idx = tid + NTH * i;
        int row = idx >> 4, c4 = idx & 15;
        float4 v = *(const float4*)(qbase + (size_t)(q0 + row) * stride + c4 * 4);
        v.x *= f2; v.y *= f2; v.z *= f2; v.w *= f2;
        uint32_t off = SWZ((uint32_t)(row * 128 + c4 * 8));
        *(uint2*)(sm + off) = make_uint2(pack_h2(v.x, v.y), pack_h2(v.z, v.w));
    }
    __syncthreads();

    // ---- Q fragments: two m-frags (rows qpair*32 .. +31) ----
    uint32_t qh0[4][4], qh1[4][4];
    {
        int rowq = qpair * 32 + (lane & 15);
        int csel = (lane >> 4) * 16;
        #pragma unroll
        for (int m = 0; m < 4; m++) {
            ldsm4(qh0[m], sb + SWZ((uint32_t)(rowq * 128 + m * 32 + csel)));
            ldsm4(qh1[m], sb + SWZ((uint32_t)((rowq + 16) * 128 + m * 32 + csel)));
        }
    }

    float o0[8][4], o1[8][4];
    #pragma unroll
    for (int j = 0; j < 8; j++)
        #pragma unroll
        for (int c = 0; c < 4; c++) { o0[j][c] = 0.f; o1[j][c] = 0.f; }
    float ls00 = 0.f, ls08 = 0.f, ls16 = 0.f, ls24 = 0.f;
    const int qg0 = q0 + qpair * 32 + gid;   // rows qg0, +8, +16, +24

    for (int nt = 0; nt <= qt; nt++) {
        const int n0 = nt * BN;
        const uint32_t stg = sb + STG0 + (uint32_t)(nt & 1) * KVBLK;

        if (nt + 1 <= qt) {
            const uint8_t* src = kvrow + (size_t)(nt + 1) * KVBLK;
            const uint32_t dst = sb + STG0 + (uint32_t)((nt + 1) & 1) * KVBLK;
            #pragma unroll
            for (int j = 0; j < 8; j++) {
                int ch = tid + j * NTH;
                cpa16(dst + ch * 16, src + ch * 16);
            }
            if (tid < 16) cpa16(dst + 16384 + tid * 16, src + 16384 + tid * 16);
            cpa_commit();
            cpa_wait<1>();
        } else {
            cpa_wait<0>();
        }
        __syncthreads();

        const float* D2 = (const float*)(sm + (stg - sb) + 16384);
        const bool diag = (nt == qt);
        const int rowk = ((lane >> 4) << 3) + (lane & 7);
        const int csub = ((lane >> 3) & 1);
        const int rowv = ((lane >> 3) & 1) * 8 + (lane & 7);
        const int csel = (lane >> 4);

        // ---- S: 32 q-rows x 32 keys; each K ldsm feeds both m-frags ----
        float s0[4][4], s1[4][4];
        #pragma unroll
        for (int jl = 0; jl < 4; jl++)
            #pragma unroll
            for (int c = 0; c < 4; c++) { s0[jl][c] = 0.f; s1[jl][c] = 0.f; }
        #pragma unroll
        for (int m = 0; m < 4; m++) {
            #pragma unroll
            for (int j2 = 0; j2 < 2; j2++) {
                int jj = 2 * khalf + j2;
                uint32_t off = SWZ((uint32_t)((jj * 16 + rowk) * 128 + (m * 2 + csub) * 16));
                uint32_t kb[4];
                ldsm4(kb, stg + off);
                mma16816(s0[2 * j2],     qh0[m], kb[0], kb[1]);
                mma16816(s0[2 * j2 + 1], qh0[m], kb[2], kb[3]);
                mma16816(s1[2 * j2],     qh1[m], kb[0], kb[1]);
                mma16816(s1[2 * j2 + 1], qh1[m], kb[2], kb[3]);
            }
        }

        // ---- softmax both m-frags, pack P to f16 ----
        uint32_t pa0[2][4], pa1[2][4];
        #pragma unroll
        for (int jl = 0; jl < 4; jl++) {
            int lc = 32 * khalf + 8 * jl + 2 * tig;
            float d0 = D2[lc], d1 = D2[lc + 1];
            int sg = n0 + lc;
            int ml = jl >> 1, hs = (jl & 1) * 2;

            float p0 = ex2f(s0[jl][0] + d0);
            float p1 = ex2f(s0[jl][1] + d1);
            float p2 = ex2f(s0[jl][2] + d0);
            float p3 = ex2f(s0[jl][3] + d1);
            if (diag) {
                if (sg     > qg0)     p0 = 0.f;
                if (sg + 1 > qg0)     p1 = 0.f;
                if (sg     > qg0 + 8) p2 = 0.f;
                if (sg + 1 > qg0 + 8) p3 = 0.f;
            }
            ls00 += p0 + p1;
            ls08 += p2 + p3;
            pa0[ml][hs]     = pack_h2(p0, p1);
            pa0[ml][hs + 1] = pack_h2(p2, p3);

            float r0 = ex2f(s1[jl][0] + d0);
            float r1 = ex2f(s1[jl][1] + d1);
            float r2 = ex2f(s1[jl][2] + d0);
            float r3 = ex2f(s1[jl][3] + d1);
            if (diag) {
                if (sg     > qg0 + 16) r0 = 0.f;
                if (sg + 1 > qg0 + 16) r1 = 0.f;
                if (sg     > qg0 + 24) r2 = 0.f;
                if (sg + 1 > qg0 + 24) r3 = 0.f;
            }
            ls16 += r0 + r1;
            ls24 += r2 + r3;
            pa1[ml][hs]     = pack_h2(r0, r1);
            pa1[ml][hs + 1] = pack_h2(r2, r3);
        }

        // ---- O += P @ V: each V ldsm feeds both m-frags ----
        #pragma unroll
        for (int ml = 0; ml < 2; ml++) {
            int mg = 2 * khalf + ml;
            #pragma unroll
            for (int jj = 0; jj < 4; jj++) {
                uint32_t off = SWZ((uint32_t)((mg * 16 + rowv) * 128 + (2 * jj + csel) * 16));
                uint32_t vb[4];
                ldsm4t(vb, stg + 8192 + off);
                mma16816(o0[2 * jj],     pa0[ml], vb[0], vb[1]);
                mma16816(o0[2 * jj + 1], pa0[ml], vb[2], vb[3]);
                mma16816(o1[2 * jj],     pa1[ml], vb[0], vb[1]);
                mma16816(o1[2 * jj + 1], pa1[ml], vb[2], vb[3]);
            }
        }
        __syncthreads();   // stage buffer free before refill
    }

    // ---- reduce l within quad ----
    ls00 += __shfl_xor_sync(0xffffffffu, ls00, 1);
    ls00 += __shfl_xor_sync(0xffffffffu, ls00, 2);
    ls08 += __shfl_xor_sync(0xffffffffu, ls08, 1);
    ls08 += __shfl_xor_sync(0xffffffffu, ls08, 2);
    ls16 += __shfl_xor_sync(0xffffffffu, ls16, 1);
    ls16 += __shfl_xor_sync(0xffffffffu, ls16, 2);
    ls24 += __shfl_xor_sync(0xffffffffu, ls24, 1);
    ls24 += __shfl_xor_sync(0xffffffffu, ls24, 2);

    // ---- cross-warp (key-half) reduction via smem (stage area is dead now) ----
    float* obuf = (float*)(sm + STG0);            // 64 rows x 64 cols f32 = 16KB
    float* lbuf = (float*)(sm + STG0 + 16384);    // 64 floats
    const int row0 = qpair * 32 + gid;

    if (khalf == 1) {
        #pragma unroll
        for (int j = 0; j < 8; j++) {
            int col = 8 * j + 2 * tig;
            *(float2*)(obuf + (row0)      * 64 + col) = make_float2(o0[j][0], o0[j][1]);
            *(float2*)(obuf + (row0 + 8)  * 64 + col) = make_float2(o0[j][2], o0[j][3]);
            *(float2*)(obuf + (row0 + 16) * 64 + col) = make_float2(o1[j][0], o1[j][1]);
            *(float2*)(obuf + (row0 + 24) * 64 + col) = make_float2(o1[j][2], o1[j][3]);
        }
        if (tig == 0) {
            lbuf[row0]      = ls00;
            lbuf[row0 + 8]  = ls08;
            lbuf[row0 + 16] = ls16;
            lbuf[row0 + 24] = ls24;
        }
    }
    __syncthreads();

    if (khalf == 0) {
        ls00 += lbuf[row0];
        ls08 += lbuf[row0 + 8];
        ls16 += lbuf[row0 + 16];
        ls24 += lbuf[row0 + 24];
        const float i00 = 1.0f / ls00;
        const float i08 = 1.0f / ls08;
        const float i16 = 1.0f / ls16;
        const float i24 = 1.0f / ls24;

        float* r00 = Og + head_off + (size_t)(qg0)      * stride;
        float* r08 = Og + head_off + (size_t)(qg0 + 8)  * stride;
        float* r16 = Og + head_off + (size_t)(qg0 + 16) * stride;
        float* r24 = Og + head_off + (size_t)(qg0 + 24) * stride;
        #pragma unroll
        for (int j = 0; j < 8; j++) {
            int col = 8 * j + 2 * tig;
            float2 a0 = *(float2*)(obuf + (row0)      * 64 + col);
            float2 a1 = *(float2*)(obuf + (row0 + 8)  * 64 + col);
            float2 a2 = *(float2*)(obuf + (row0 + 16) * 64 + col);
            float2 a3 = *(float2*)(obuf + (row0 + 24) * 64 + col);
            *(float2*)(r00 + col) = make_float2((o0[j][0] + a0.x) * i00, (o0[j][1] + a0.y) * i00);
            *(float2*)(r08 + col) = make_float2((o0[j][2] + a1.x) * i08, (o0[j][3] + a1.y) * i08);
            *(float2*)(r16 + col) = make_float2((o1[j][0] + a2.x) * i16, (o1[j][1] + a2.y) * i16);
            *(float2*)(r24 + col) = make_float2((o1[j][2] + a3.x) * i24, (o1[j][3] + a3.y) * i24);
        }
    }
}

extern "C" void kernel_launch(void* const* d_in, const int* in_sizes, int n_in,
                              void* d_out, int out_size) {
    const float* Q     = (const float*)d_in[0];
    const float* K     = (const float*)d_in[1];
    const float* V     = (const float*)d_in[2];
    const float* tau   = (const float*)d_in[3];
    const float* delta = (const float*)d_in[4];
    float* O = (float*)d_out;

    const int B = in_sizes[3];
    const int L = in_sizes[4] / B;
    const int H = in_sizes[0] / (B * L * 64);
    const int BH = B * H;
    const int numQT = L / 64;

    static bool attr_set = false;
    if (!attr_set) {
        cudaFuncSetAttribute(dsattn_mma, cudaFuncAttributeMaxDynamicSharedMemorySize, SMEM_MAIN);
        attr_set = true;
    }

    prep_kernel<<<BH * numQT, NTH>>>(K, V, delta, B, L, H);
    dsattn_mma<<<numQT * BH, NTH, SMEM_MAIN>>>(Q, tau, O, B, L, H);
}

// round 15
// speedup vs baseline: 1.3228x; 1.1486x over previous
#include <cuda_runtime.h>
#include <cuda_fp16.h>
#include <cstdint>

#define NTH 128
#define BN 64
#define MAX_BH 32
#define MAX_T  32

#define KVBLK 16640          // KH 8192 + V 8192 + D2(f16) 128 + pad

// static scratch (allowed: __device__ globals, no runtime alloc)
__device__ __align__(1024) uint8_t g_kv[(size_t)MAX_BH * MAX_T * KVBLK];

#define SWZ(x) ((x) ^ (((x) >> 3) & 0x70))
#define ONESH2 0x3C003C00u   // f16x2 {1.0, 1.0}

__device__ __forceinline__ uint32_t smem_u32(const void* p) {
    uint32_t a;
    asm("{ .reg .u64 t; cvta.to.shared.u64 t, %1; cvt.u32.u64 %0, t; }" : "=r"(a) : "l"(p));
    return a;
}
__device__ __forceinline__ uint32_t pack_h2(float a, float b) {
    uint32_t d; asm("cvt.rn.f16x2.f32 %0, %1, %2;" : "=r"(d) : "f"(b), "f"(a)); return d;
}
__device__ __forceinline__ uint32_t hadd2(uint32_t a, uint32_t b) {
    uint32_t d; asm("add.rn.f16x2 %0, %1, %2;" : "=r"(d) : "r"(a), "r"(b)); return d;
}
__device__ __forceinline__ uint32_t ex2h2(uint32_t a) {
    uint32_t d; asm("ex2.approx.f16x2 %0, %1;" : "=r"(d) : "r"(a)); return d;
}
__device__ __forceinline__ void ldsm4(uint32_t* r, uint32_t addr) {
    asm volatile("ldmatrix.sync.aligned.m8n8.x4.shared.b16 {%0,%1,%2,%3}, [%4];"
        : "=r"(r[0]), "=r"(r[1]), "=r"(r[2]), "=r"(r[3]) : "r"(addr));
}
__device__ __forceinline__ void ldsm4t(uint32_t* r, uint32_t addr) {
    asm volatile("ldmatrix.sync.aligned.m8n8.x4.trans.shared.b16 {%0,%1,%2,%3}, [%4];"
        : "=r"(r[0]), "=r"(r[1]), "=r"(r[2]), "=r"(r[3]) : "r"(addr));
}
// f32-accumulator mma
__device__ __forceinline__ void mma16816(float* c, const uint32_t* a, uint32_t b0, uint32_t b1) {
    asm volatile("mma.sync.aligned.m16n8k16.row.col.f32.f16.f16.f32 "
        "{%0,%1,%2,%3}, {%4,%5,%6,%7}, {%8,%9}, {%0,%1,%2,%3};"
        : "+f"(c[0]), "+f"(c[1]), "+f"(c[2]), "+f"(c[3])
        : "r"(a[0]), "r"(a[1]), "r"(a[2]), "r"(a[3]), "r"(b0), "r"(b1));
}
// f16-accumulator mma (packed f16x2 C/D, 2 regs)
__device__ __forceinline__ void mma16816h(uint32_t* c, const uint32_t* a, uint32_t b0, uint32_t b1) {
    asm volatile("mma.sync.aligned.m16n8k16.row.col.f16.f16.f16.f16 "
        "{%0,%1}, {%2,%3,%4,%5}, {%6,%7}, {%0,%1};"
        : "+r"(c[0]), "+r"(c[1])
        : "r"(a[0]), "r"(a[1]), "r"(a[2]), "r"(a[3]), "r"(b0), "r"(b1));
}
__device__ __forceinline__ void cpa16(uint32_t s, const void* g) {
    asm volatile("cp.async.cg.shared.global [%0], [%1], 16;" :: "r"(s), "l"(g));
}
__device__ __forceinline__ void cpa_commit() {
    asm volatile("cp.async.commit_group;" ::: "memory");
}
template <int N>
__device__ __forceinline__ void cpa_wait() {
    asm volatile("cp.async.wait_group %0;" :: "n"(N) : "memory");
}

// ---------------- preprocess: K->f16, V->f16, d2(f16x2); smem-image layout --------
__global__ void __launch_bounds__(NTH)
prep_kernel(const float* __restrict__ Kg, const float* __restrict__ Vg,
            const float* __restrict__ deltag, int B, int L, int H)
{
    const int BH = B * H;
    const int numT = L / 64;
    const int bid = blockIdx.x;
    const int t  = bid / BH;
    const int bh = bid % BH;
    const int b = bh / H, h = bh % H;
    const int tid = threadIdx.x;

    const int stride = H * 64;
    const size_t head_off = (size_t)b * L * stride + (size_t)h * 64;
    const int r0 = t * 64;

    uint8_t* kvb = g_kv + (size_t)(bh * numT + t) * KVBLK;

    #pragma unroll
    for (int i = 0; i < 8; i++) {
        int idx = tid + NTH * i;            // 1024 float4s per 64x64 tile
        int row = idx >> 4, c4 = idx & 15;
        uint32_t off = SWZ((uint32_t)(row * 128 + c4 * 8));
        const size_t goff = head_off + (size_t)(r0 + row) * stride + c4 * 4;

        float4 k = *(const float4*)(Kg + goff);
        *(uint2*)(kvb + off) = make_uint2(pack_h2(k.x, k.y), pack_h2(k.z, k.w));

        float4 vv = *(const float4*)(Vg + goff);
        *(uint2*)(kvb + 8192 + off) = make_uint2(pack_h2(vv.x, vv.y), pack_h2(vv.z, vv.w));
    }
    const float LOG2E = 1.4426950408889634f;
    if (tid < 32) {
        float d0 = deltag[(size_t)b * L + r0 + 2 * tid]     * (0.125f * LOG2E);
        float d1 = deltag[(size_t)b * L + r0 + 2 * tid + 1] * (0.125f * LOG2E);
        ((uint32_t*)(kvb + 16384))[tid] = pack_h2(d0, d1);
    }
}

// ---------------- main: warp=(qpair,khalf); 3-stage cp.async; packed softmax ----------
#define STG0 8192             // stages after Q region (QH 8KB)
#define SMEM_MAIN (8192 + 3 * KVBLK + 1024)

__global__ void __launch_bounds__(NTH, 3)
dsattn_mma(const float* __restrict__ Qg, const float* __restrict__ taug,
           float* __restrict__ Og, int B, int L, int H)
{
    extern __shared__ __align__(1024) char smraw[];
    const uint32_t raw32 = smem_u32(smraw);
    const uint32_t sb = (raw32 + 1023u) & ~1023u;
    char* sm = smraw + (sb - raw32);

    const int tid  = threadIdx.x;
    const int wid  = tid >> 5;
    const int lane = tid & 31;
    const int gid  = lane >> 2;
    const int tig  = lane & 3;
    const int qpair = wid >> 1;          // 0: q-rows 0-31, 1: q-rows 32-63
    const int khalf = wid & 1;           // 0: keys 0-31 of tile, 1: keys 32-63

    const int numQT = L / 64;
    const int BH = B * H;
    const int qt = numQT - 1 - ((int)blockIdx.x / BH);   // LPT: big q-tiles first
    const int bh = (int)blockIdx.x % BH;
    const int b = bh / H, h = bh % H;

    const int stride = H * 64;
    const size_t head_off = (size_t)b * L * stride + (size_t)h * 64;
    const float* qbase = Qg + head_off;
    const uint8_t* kvrow = g_kv + (size_t)bh * numQT * KVBLK;

    const float LOG2E = 1.4426950408889634f;
    const float f2 = taug[b] * 0.125f * LOG2E;
    const int q0 = qt * 64;

    // ---- prologue: prefetch tiles 0 and 1 (separate groups), convert Q behind ----
    {
        #pragma unroll
        for (int j = 0; j < 8; j++) {
            int ch = tid + j * NTH;
            cpa16(sb + STG0 + ch * 16, kvrow + ch * 16);
        }
        if (tid < 16) cpa16(sb + STG0 + 16384 + tid * 16, kvrow + 16384 + tid * 16);
        cpa_commit();
        if (qt >= 1) {
            const uint8_t* src = kvrow + KVBLK;
            const uint32_t dst = sb + STG0 + KVBLK;
            #pragma unroll
            for (int j = 0; j < 8; j++) {
                int ch = tid + j * NTH;
                cpa16(dst + ch * 16, src + ch * 16);
            }
            if (tid < 16) cpa16(dst + 16384 + tid * 16, src + 16384 + tid * 16);
            cpa_commit();
        }
    }

    // ---- Q tile (64 rows): scale, f16, swizzled panel ----
    #pragma unroll
    for (int i = 0; i < 8; i++) {
        int idx = tid + NTH * i;
        int row = idx >> 4, c4 = idx & 15;
        float4 v = *(const float4*)(qbase + (size_t)(q0 + row) * stride + c4 * 4);
        v.x *= f2; v.y *= f2; v.z *= f2; v.w *= f2;
        uint32_t off = SWZ((uint32_t)(row * 128 + c4 * 8));
        *(uint2*)(sm + off) = make_uint2(pack_h2(v.x, v.y), pack_h2(v.z, v.w));
    }
    __syncthreads();

    // ---- Q fragments: two m-frags (rows qpair*32 .. +31) ----
    uint32_t qh0[4][4], qh1[4][4];
    {
        int rowq = qpair * 32 + (lane & 15);
        int csel = (lane >> 4) * 16;
        #pragma unroll
        for (int m = 0; m < 4; m++) {
            ldsm4(qh0[m], sb + SWZ((uint32_t)(rowq * 128 + m * 32 + csel)));
            ldsm4(qh1[m], sb + SWZ((uint32_t)((rowq + 16) * 128 + m * 32 + csel)));
        }
    }

    float o0[8][4], o1[8][4];
    #pragma unroll
    for (int j = 0; j < 8; j++)
        #pragma unroll
        for (int c = 0; c < 4; c++) { o0[j][c] = 0.f; o1[j][c] = 0.f; }
    float lacc0[4] = {0.f, 0.f, 0.f, 0.f};
    float lacc1[4] = {0.f, 0.f, 0.f, 0.f};
    const int qg0 = q0 + qpair * 32 + gid;   // rows qg0, +8, +16, +24

    const int rowk = ((lane >> 4) << 3) + (lane & 7);
    const int csub = ((lane >> 3) & 1);
    const int rowv = ((lane >> 3) & 1) * 8 + (lane & 7);
    const int csel2 = (lane >> 4);

    for (int nt = 0; nt <= qt; nt++) {
        const int n0 = nt * BN;
        const uint32_t stg = sb + STG0 + (uint32_t)(nt % 3) * KVBLK;

        // stage nt ready + visible; also gates reuse of stage (nt+2)%3 for prefetch below
        if (nt + 1 <= qt) cpa_wait<1>(); else cpa_wait<0>();
        __syncthreads();

        const uint32_t* D2h = (const uint32_t*)(sm + (stg - sb) + 16384);
        const bool diag = (nt == qt);

        // ---- S (f16 acc): 32 q-rows x 32 keys; each K ldsm feeds both m-frags ----
        uint32_t s0p[8], s1p[8];
        #pragma unroll
        for (int i = 0; i < 8; i++) { s0p[i] = 0u; s1p[i] = 0u; }
        #pragma unroll
        for (int m = 0; m < 4; m++) {
            #pragma unroll
            for (int j2 = 0; j2 < 2; j2++) {
                int jj = 2 * khalf + j2;
                uint32_t off = SWZ((uint32_t)((jj * 16 + rowk) * 128 + (m * 2 + csub) * 16));
                uint32_t kb[4];
                ldsm4(kb, stg + off);
                mma16816h(&s0p[4 * j2],     qh0[m], kb[0], kb[1]);
                mma16816h(&s0p[4 * j2 + 2], qh0[m], kb[2], kb[3]);
                mma16816h(&s1p[4 * j2],     qh1[m], kb[0], kb[1]);
                mma16816h(&s1p[4 * j2 + 2], qh1[m], kb[2], kb[3]);
            }
        }

        // ---- packed softmax: p = exp2(s + d2), mask by AND, output = PV A-frag ----
        uint32_t pa0[2][4], pa1[2][4];
        #pragma unroll
        for (int jl = 0; jl < 4; jl++) {
            int lc = 32 * khalf + 8 * jl + 2 * tig;
            uint32_t dpair = D2h[16 * khalf + 4 * jl + tig];
            int ml = jl >> 1, hs = (jl & 1) * 2;

            uint32_t e00 = ex2h2(hadd2(s0p[2 * jl],     dpair));  // rows gid
            uint32_t e01 = ex2h2(hadd2(s0p[2 * jl + 1], dpair));  // rows gid+8
            uint32_t e10 = ex2h2(hadd2(s1p[2 * jl],     dpair));  // rows gid+16
            uint32_t e11 = ex2h2(hadd2(s1p[2 * jl + 1], dpair));  // rows gid+24
            if (diag) {
                int sg = n0 + lc;
                uint32_t m00 = (sg > qg0      ? 0u : 0xFFFFu) | (sg + 1 > qg0      ? 0u : 0xFFFF0000u);
                uint32_t m01 = (sg > qg0 + 8  ? 0u : 0xFFFFu) | (sg + 1 > qg0 + 8  ? 0u : 0xFFFF0000u);
                uint32_t m10 = (sg > qg0 + 16 ? 0u : 0xFFFFu) | (sg + 1 > qg0 + 16 ? 0u : 0xFFFF0000u);
                uint32_t m11 = (sg > qg0 + 24 ? 0u : 0xFFFFu) | (sg + 1 > qg0 + 24 ? 0u : 0xFFFF0000u);
                e00 &= m00; e01 &= m01; e10 &= m10; e11 &= m11;
            }
            pa0[ml][hs]     = e00;
            pa0[ml][hs + 1] = e01;
            pa1[ml][hs]     = e10;
            pa1[ml][hs + 1] = e11;
        }

        // ---- O += P @ V; lsum via ones-MMA ----
        #pragma unroll
        for (int ml = 0; ml < 2; ml++) {
            int mg = 2 * khalf + ml;
            #pragma unroll
            for (int jj = 0; jj < 4; jj++) {
                uint32_t off = SWZ((uint32_t)((mg * 16 + rowv) * 128 + (2 * jj + csel2) * 16));
                uint32_t vb[4];
                ldsm4t(vb, stg + 8192 + off);
                mma16816(o0[2 * jj],     pa0[ml], vb[0], vb[1]);
                mma16816(o0[2 * jj + 1], pa0[ml], vb[2], vb[3]);
                mma16816(o1[2 * jj],     pa1[ml], vb[0], vb[1]);
                mma16816(o1[2 * jj + 1], pa1[ml], vb[2], vb[3]);
            }
            mma16816(lacc0, pa0[ml], ONESH2, ONESH2);
            mma16816(lacc1, pa1[ml], ONESH2, ONESH2);
        }

        // ---- prefetch tile nt+2 into stage (nt+2)%3 (freed by this tile's top sync) ----
        if (nt + 2 <= qt) {
            const uint8_t* src = kvrow + (size_t)(nt + 2) * KVBLK;
            const uint32_t dst = sb + STG0 + (uint32_t)((nt + 2) % 3) * KVBLK;
            #pragma unroll
            for (int j = 0; j < 8; j++) {
                int ch = tid + j * NTH;
                cpa16(dst + ch * 16, src + ch * 16);
            }
            if (tid < 16) cpa16(dst + 16384 + tid * 16, src + 16384 + tid * 16);
            cpa_commit();
        }
    }

    // lsum fragments: all quad columns hold the same value
    float ls00 = lacc0[0], ls08 = lacc0[2], ls16 = lacc1[0], ls24 = lacc1[2];

    // ---- cross-warp (key-half) reduction via smem (stage0 region is dead now) ----
    __syncthreads();
    float* obuf = (float*)(sm + STG0);            // 64 x 64 f32 = 16KB
    float* lbuf = (float*)(sm + STG0 + 16384);    // 64 floats
    const int row0 = qpair * 32 + gid;

    if (khalf == 1) {
        #pragma unroll
        for (int j = 0; j < 8; j++) {
            int col = 8 * j + 2 * tig;
            *(float2*)(obuf + (row0)      * 64 + col) = make_float2(o0[j][0], o0[j][1]);
            *(float2*)(obuf + (row0 + 8)  * 64 + col) = make_float2(o0[j][2], o0[j][3]);
            *(float2*)(obuf + (row0 + 16) * 64 + col) = make_float2(o1[j][0], o1[j][1]);
            *(float2*)(obuf + (row0 + 24) * 64 + col) = make_float2(o1[j][2], o1[j][3]);
        }
        if (tig == 0) {
            lbuf[row0]      = ls00;
            lbuf[row0 + 8]  = ls08;
            lbuf[row0 + 16] = ls16;
            lbuf[row0 + 24] = ls24;
        }
    }
    __syncthreads();

    if (khalf == 0) {
        ls00 += lbuf[row0];
        ls08 += lbuf[row0 + 8];
        ls16 += lbuf[row0 + 16];
        ls24 += lbuf[row0 + 24];
        const float i00 = 1.0f / ls00;
        const float i08 = 1.0f / ls08;
        const float i16 = 1.0f / ls16;
        const float i24 = 1.0f / ls24;

        float* r00 = Og + head_off + (size_t)(qg0)      * stride;
        float* r08 = Og + head_off + (size_t)(qg0 + 8)  * stride;
        float* r16 = Og + head_off + (size_t)(qg0 + 16) * stride;
        float* r24 = Og + head_off + (size_t)(qg0 + 24) * stride;
        #pragma unroll
        for (int j = 0; j < 8; j++) {
            int col = 8 * j + 2 * tig;
            float2 a0 = *(float2*)(obuf + (row0)      * 64 + col);
            float2 a1 = *(float2*)(obuf + (row0 + 8)  * 64 + col);
            float2 a2 = *(float2*)(obuf + (row0 + 16) * 64 + col);
            float2 a3 = *(float2*)(obuf + (row0 + 24) * 64 + col);
            *(float2*)(r00 + col) = make_float2((o0[j][0] + a0.x) * i00, (o0[j][1] + a0.y) * i00);
            *(float2*)(r08 + col) = make_float2((o0[j][2] + a1.x) * i08, (o0[j][3] + a1.y) * i08);
            *(float2*)(r16 + col) = make_float2((o1[j][0] + a2.x) * i16, (o1[j][1] + a2.y) * i16);
            *(float2*)(r24 + col) = make_float2((o1[j][2] + a3.x) * i24, (o1[j][3] + a3.y) * i24);
        }
    }
}

extern "C" void kernel_launch(void* const* d_in, const int* in_sizes, int n_in,
                              void* d_out, int out_size) {
    const float* Q     = (const float*)d_in[0];
    const float* K     = (const float*)d_in[1];
    const float* V     = (const float*)d_in[2];
    const float* tau   = (const float*)d_in[3];
    const float* delta = (const float*)d_in[4];
    float* O = (float*)d_out;

    const int B = in_sizes[3];
    const int L = in_sizes[4] / B;
    const int H = in_sizes[0] / (B * L * 64);
    const int BH = B * H;
    const int numQT = L / 64;

    static bool attr_set = false;
    if (!attr_set) {
        cudaFuncSetAttribute(dsattn_mma, cudaFuncAttributeMaxDynamicSharedMemorySize, SMEM_MAIN);
        attr_set = true;
    }

    prep_kernel<<<BH * numQT, NTH>>>(K, V, delta, B, L, H);
    dsattn_mma<<<numQT * BH, NTH, SMEM_MAIN>>>(Q, tau, O, B, L, H);
}